// round 1
// baseline (speedup 1.0000x reference)
#include <cuda_runtime.h>
#include <cuda_bf16.h>
#include <cstdint>

// ---------------- problem constants ----------------
#define C 128
#define H 8
#define DD 16
#define OUTC 64
#define NLAYER 2

static const int NNh[3]  = {30000, 60000, 6000};
static const int XOFF[3] = {0, 30000, 90000};
#define NTOT 96000
static const int NEh[4]  = {200000, 300000, 200000, 100000};
static const int EOFF[4] = {0, 200000, 500000, 700000};
#define ETOT 800000
static const int ESRC[4] = {0, 1, 1, 2};
static const int EDST[4] = {1, 1, 2, 0};
// k_et / v_et segments (per edge type, sized by src-type node count)
static const int KOFF[4] = {0, 30000, 90000, 150000};
#define KETROWS 156000
// per-edge-type softmax stats segments (sized by dst-type node count)
static const int DOFF[4] = {0, 60000, 120000, 126000};
#define DROWS 156000

// ---------------- scratch (device globals; no allocation allowed) ----------------
__device__ float    g_xs   [NTOT * C];
__device__ float    g_q    [NTOT * C];
__device__ float    g_gbuf [NTOT * C];
__device__ float    g_agg  [NTOT * C];
__device__ float    g_ket  [KETROWS * C];
__device__ float    g_vet  [KETROWS * C];
__device__ float    g_alpha[ETOT * H];
__device__ float    g_den  [DROWS * H];
__device__ unsigned g_amax [DROWS * H];
__device__ float    g_kwc  [NLAYER * 4 * C * C];
__device__ float    g_vwc  [NLAYER * 4 * C * C];
__device__ float    g_kbc  [NLAYER * 4 * C];
__device__ float    g_vbc  [NLAYER * 4 * C];

// ---------------- helpers ----------------
__device__ __forceinline__ unsigned fenc(float f) {
    unsigned u = __float_as_uint(f);
    return (u & 0x80000000u) ? ~u : (u | 0x80000000u);
}
__device__ __forceinline__ float fdec(unsigned u) {
    return (u & 0x80000000u) ? __uint_as_float(u ^ 0x80000000u) : __uint_as_float(~u);
}
__device__ __forceinline__ float gelu_tanh(float x) {
    float x3 = x * x * x;
    return 0.5f * x * (1.0f + tanhf(0.7978845608028654f * (x + 0.044715f * x3)));
}

// ---------------- combined K/V weights:  kwc = kw @ blockdiag(a_rel) ----------------
// kwc[l,et][c, h*16+f] = sum_d kw[l,si][c, h*16+d] * a_rel[l,et,h,d,f]
__global__ void wcomb_kernel(const float* __restrict__ kw, const float* __restrict__ kb,
                             const float* __restrict__ vw, const float* __restrict__ vb,
                             const float* __restrict__ a_rel, const float* __restrict__ m_rel)
{
    int b  = blockIdx.x;          // 0..7 == l*4+et
    int l  = b >> 2, et = b & 3;
    int si = (et == 0) ? 0 : ((et == 3) ? 2 : 1);
    const float* KW = kw + (size_t)(l * 3 + si) * C * C;
    const float* VW = vw + (size_t)(l * 3 + si) * C * C;
    const float* KB = kb + (size_t)(l * 3 + si) * C;
    const float* VB = vb + (size_t)(l * 3 + si) * C;
    const float* AR = a_rel + (size_t)b * H * DD * DD;
    const float* MR = m_rel + (size_t)b * H * DD * DD;
    float* KWC = g_kwc + (size_t)b * C * C;
    float* VWC = g_vwc + (size_t)b * C * C;

    for (int idx = threadIdx.x; idx < C * C; idx += blockDim.x) {
        int c = idx >> 7, hf = idx & 127, h = hf >> 4, f = hf & 15;
        float sk = 0.f, sv = 0.f;
        #pragma unroll
        for (int d = 0; d < DD; d++) {
            float ar = AR[(h * DD + d) * DD + f];
            float mr = MR[(h * DD + d) * DD + f];
            sk += KW[c * C + h * DD + d] * ar;
            sv += VW[c * C + h * DD + d] * mr;
        }
        KWC[idx] = sk; VWC[idx] = sv;
    }
    if (threadIdx.x < C) {
        int hf = threadIdx.x, h = hf >> 4, f = hf & 15;
        float sk = 0.f, sv = 0.f;
        #pragma unroll
        for (int d = 0; d < DD; d++) {
            sk += KB[h * DD + d] * AR[(h * DD + d) * DD + f];
            sv += VB[h * DD + d] * MR[(h * DD + d) * DD + f];
        }
        g_kbc[b * C + hf] = sk; g_vbc[b * C + hf] = sv;
    }
}

// ---------------- GEMM: Out[M,BN] = A[M,128] @ W[128,BN] (+bias, epilogue) ----------------
// EPI 0: +bias  | EPI 1: relu(+bias) | EPI 2: beta*(+bias) + (1-beta)*skipx, relu
template<int BN, int EPI>
__global__ void __launch_bounds__(256)
gemm_k128(const float* __restrict__ A, const float* __restrict__ W,
          const float* __restrict__ bias, float* __restrict__ Out, int M,
          const float* __restrict__ skipx, const float* __restrict__ skipv)
{
    constexpr int CT = BN / 4;        // threads along cols
    constexpr int RG = 256 / CT;      // row groups
    constexpr int BM = RG * 8;        // rows per block (64 or 128)
    constexpr int BK = 32;
    constexpr int AP = BM + 4;        // padded row length of As

    __shared__ float As[BK][AP];
    __shared__ float Bs[BK][BN];

    int tid  = threadIdx.x;
    int row0 = blockIdx.x * BM;
    int trow = (tid / CT) * 8;
    int tcol = (tid % CT) * 4;

    float acc[8][4];
    #pragma unroll
    for (int r = 0; r < 8; r++)
        #pragma unroll
        for (int c = 0; c < 4; c++) acc[r][c] = 0.f;

    for (int k0 = 0; k0 < 128; k0 += BK) {
        // A tile: BM x BK  (store transposed As[k][row])
        #pragma unroll
        for (int i = 0; i < (BM * 8) / 256; ++i) {
            int id = tid + i * 256;
            int r  = id >> 3;
            int kq = id & 7;
            float4 v = make_float4(0.f, 0.f, 0.f, 0.f);
            int gr = row0 + r;
            if (gr < M) v = *(const float4*)(A + (size_t)gr * 128 + k0 + kq * 4);
            As[kq * 4 + 0][r] = v.x;
            As[kq * 4 + 1][r] = v.y;
            As[kq * 4 + 2][r] = v.z;
            As[kq * 4 + 3][r] = v.w;
        }
        // B tile: BK x BN
        #pragma unroll
        for (int i = 0; i < (8 * BN) / 256; ++i) {
            int id = tid + i * 256;
            int kr = id / CT;
            int c4 = (id % CT) * 4;
            *(float4*)&Bs[kr][c4] = *(const float4*)(W + (size_t)(k0 + kr) * BN + c4);
        }
        __syncthreads();
        #pragma unroll
        for (int k = 0; k < BK; ++k) {
            float4 b = *(float4*)&Bs[k][tcol];
            float a[8];
            #pragma unroll
            for (int r = 0; r < 8; r++) a[r] = As[k][trow + r];
            #pragma unroll
            for (int r = 0; r < 8; r++) {
                acc[r][0] += a[r] * b.x;
                acc[r][1] += a[r] * b.y;
                acc[r][2] += a[r] * b.z;
                acc[r][3] += a[r] * b.w;
            }
        }
        __syncthreads();
    }

    float b0 = bias[tcol], b1 = bias[tcol + 1], b2 = bias[tcol + 2], b3 = bias[tcol + 3];
    float beta = 0.f, omb = 0.f;
    if (EPI == 2) {
        float sv = *skipv;
        beta = 1.f / (1.f + __expf(-sv));
        omb  = 1.f - beta;
    }
    #pragma unroll
    for (int r = 0; r < 8; r++) {
        int gr = row0 + trow + r;
        if (gr >= M) break;
        float4 o;
        o.x = acc[r][0] + b0; o.y = acc[r][1] + b1;
        o.z = acc[r][2] + b2; o.w = acc[r][3] + b3;
        if (EPI == 1) {
            o.x = fmaxf(o.x, 0.f); o.y = fmaxf(o.y, 0.f);
            o.z = fmaxf(o.z, 0.f); o.w = fmaxf(o.w, 0.f);
        }
        if (EPI == 2) {
            float4 sx = *(const float4*)(skipx + (size_t)gr * 128 + tcol);
            o.x = fmaxf(beta * o.x + omb * sx.x, 0.f);
            o.y = fmaxf(beta * o.y + omb * sx.y, 0.f);
            o.z = fmaxf(beta * o.z + omb * sx.z, 0.f);
            o.w = fmaxf(beta * o.w + omb * sx.w, 0.f);
        }
        *(float4*)(Out + (size_t)gr * BN + tcol) = o;
    }
}

// ---------------- edge pass 1: raw attention logits + segment max ----------------
__global__ void __launch_bounds__(256)
edge_alpha_kernel(const float* __restrict__ qb, const float* __restrict__ ketb,
                  const int* __restrict__ src, const int* __restrict__ dst, int E,
                  const float* __restrict__ prel,
                  float* __restrict__ alpha, unsigned* __restrict__ amax)
{
    int e = blockIdx.x * 8 + (threadIdx.x >> 5);
    if (e >= E) return;
    int lane = threadIdx.x & 31;
    int s = src[e], d = dst[e];
    float4 qv = ((const float4*)(qb  + (size_t)d * 128))[lane];
    float4 kv = ((const float4*)(ketb + (size_t)s * 128))[lane];
    float p = qv.x * kv.x + qv.y * kv.y + qv.z * kv.z + qv.w * kv.w;
    p += __shfl_xor_sync(0xffffffffu, p, 1);
    p += __shfl_xor_sync(0xffffffffu, p, 2);
    int h = lane >> 2;
    if ((lane & 3) == 0) {
        float a = p * 0.25f * prel[h];   // scale = 1/sqrt(16)
        alpha[(size_t)e * H + h] = a;
        atomicMax(&amax[(size_t)d * H + h], fenc(a));
    }
}

// ---------------- edge pass 2: exp + segment denominator ----------------
__global__ void __launch_bounds__(256)
edge_exp_kernel(const int* __restrict__ dst, int E,
                const unsigned* __restrict__ amax,
                float* __restrict__ alpha, float* __restrict__ den)
{
    int i = blockIdx.x * 256 + threadIdx.x;
    if (i >= E * H) return;
    int e = i >> 3, h = i & 7;
    int d = dst[e];
    float m = fdec(amax[(size_t)d * H + h]);
    float ex = __expf(alpha[i] - m);
    alpha[i] = ex;
    atomicAdd(&den[(size_t)d * H + h], ex);
}

// ---------------- edge pass 3: weighted message aggregation ----------------
__global__ void __launch_bounds__(256)
edge_msg_kernel(const float* __restrict__ vetb,
                const int* __restrict__ src, const int* __restrict__ dst, int E,
                const float* __restrict__ alpha, const float* __restrict__ den,
                float* __restrict__ agg)
{
    int e = blockIdx.x * 8 + (threadIdx.x >> 5);
    if (e >= E) return;
    int lane = threadIdx.x & 31;
    int s = src[e], d = dst[e];
    int h = lane >> 2;
    float ex = alpha[(size_t)e * H + h];
    float dn = den[(size_t)d * H + h];
    float w  = ex / (dn + 1e-16f);
    float4 v = ((const float4*)(vetb + (size_t)s * 128))[lane];
    v.x *= w; v.y *= w; v.z *= w; v.w *= w;
    atomicAdd((float4*)(agg + (size_t)d * 128 + lane * 4), v);
}

// ---------------- gelu over aggregated messages ----------------
__global__ void __launch_bounds__(256)
finalize_gelu(const float* __restrict__ agg, float* __restrict__ g, int ntot)
{
    int i = blockIdx.x * 256 + threadIdx.x;   // float4 index
    if (i >= ntot * 32) return;
    float4 v = ((const float4*)agg)[i];
    float4 o;
    o.x = gelu_tanh(v.x); o.y = gelu_tanh(v.y);
    o.z = gelu_tanh(v.z); o.w = gelu_tanh(v.w);
    ((float4*)g)[i] = o;
}

// ---------------- host orchestration ----------------
extern "C" void kernel_launch(void* const* d_in, const int* in_sizes, int n_in,
                              void* d_out, int out_size)
{
    const float* x_in[3] = {(const float*)d_in[0], (const float*)d_in[1], (const float*)d_in[2]};
    const int* esrc[4] = {(const int*)d_in[3], (const int*)d_in[5], (const int*)d_in[7], (const int*)d_in[9]};
    const int* edst[4] = {(const int*)d_in[4], (const int*)d_in[6], (const int*)d_in[8], (const int*)d_in[10]};
    const float* lin_w = (const float*)d_in[11];
    const float* lin_b = (const float*)d_in[12];
    const float* kw    = (const float*)d_in[13];
    const float* qw    = (const float*)d_in[14];
    const float* vw    = (const float*)d_in[15];
    const float* aw    = (const float*)d_in[16];
    const float* kb    = (const float*)d_in[17];
    const float* qb    = (const float*)d_in[18];
    const float* vb    = (const float*)d_in[19];
    const float* ab    = (const float*)d_in[20];
    const float* a_rel = (const float*)d_in[21];
    const float* m_rel = (const float*)d_in[22];
    const float* p_rel = (const float*)d_in[23];
    const float* skip  = (const float*)d_in[24];
    const float* out_w = (const float*)d_in[25];
    const float* out_b = (const float*)d_in[26];
    float* out = (float*)d_out;

    float *xs, *q, *gbuf, *agg, *ket, *vet, *alpha, *den, *kwc, *vwc, *kbc, *vbc;
    unsigned* amax;
    cudaGetSymbolAddress((void**)&xs,   g_xs);
    cudaGetSymbolAddress((void**)&q,    g_q);
    cudaGetSymbolAddress((void**)&gbuf, g_gbuf);
    cudaGetSymbolAddress((void**)&agg,  g_agg);
    cudaGetSymbolAddress((void**)&ket,  g_ket);
    cudaGetSymbolAddress((void**)&vet,  g_vet);
    cudaGetSymbolAddress((void**)&alpha,g_alpha);
    cudaGetSymbolAddress((void**)&den,  g_den);
    cudaGetSymbolAddress((void**)&amax, g_amax);
    cudaGetSymbolAddress((void**)&kwc,  g_kwc);
    cudaGetSymbolAddress((void**)&vwc,  g_vwc);
    cudaGetSymbolAddress((void**)&kbc,  g_kbc);
    cudaGetSymbolAddress((void**)&vbc,  g_vbc);

    // precompute combined K/V weights (a_rel / m_rel folded in)
    wcomb_kernel<<<8, 256>>>(kw, kb, vw, vb, a_rel, m_rel);

    // input linear + relu
    for (int i = 0; i < 3; i++) {
        dim3 grid((NNh[i] + 63) / 64);
        gemm_k128<128, 1><<<grid, 256>>>(x_in[i], lin_w + (size_t)i * C * C,
                                         lin_b + i * C, xs + (size_t)XOFF[i] * C,
                                         NNh[i], nullptr, nullptr);
    }

    for (int l = 0; l < NLAYER; l++) {
        // Q projection per node type
        for (int i = 0; i < 3; i++) {
            dim3 grid((NNh[i] + 63) / 64);
            gemm_k128<128, 0><<<grid, 256>>>(xs + (size_t)XOFF[i] * C,
                                             qw + (size_t)(l * 3 + i) * C * C,
                                             qb + (l * 3 + i) * C,
                                             q + (size_t)XOFF[i] * C,
                                             NNh[i], nullptr, nullptr);
        }
        // K_et / V_et projections per edge type (combined weights)
        for (int et = 0; et < 4; et++) {
            int si = ESRC[et];
            dim3 grid((NNh[si] + 63) / 64);
            gemm_k128<128, 0><<<grid, 256>>>(xs + (size_t)XOFF[si] * C,
                                             kwc + (size_t)(l * 4 + et) * C * C,
                                             kbc + (l * 4 + et) * C,
                                             ket + (size_t)KOFF[et] * C,
                                             NNh[si], nullptr, nullptr);
            gemm_k128<128, 0><<<grid, 256>>>(xs + (size_t)XOFF[si] * C,
                                             vwc + (size_t)(l * 4 + et) * C * C,
                                             vbc + (l * 4 + et) * C,
                                             vet + (size_t)KOFF[et] * C,
                                             NNh[si], nullptr, nullptr);
        }
        // clear stats + agg
        cudaMemsetAsync(agg,  0, (size_t)NTOT * C * sizeof(float));
        cudaMemsetAsync(den,  0, (size_t)DROWS * H * sizeof(float));
        cudaMemsetAsync(amax, 0, (size_t)DROWS * H * sizeof(unsigned));

        // pass 1: logits + segment max (per edge type)
        for (int et = 0; et < 4; et++) {
            int di = EDST[et];
            dim3 grid((NEh[et] + 7) / 8);
            edge_alpha_kernel<<<grid, 256>>>(q + (size_t)XOFF[di] * C,
                                             ket + (size_t)KOFF[et] * C,
                                             esrc[et], edst[et], NEh[et],
                                             p_rel + (l * 4 + et) * H,
                                             alpha + (size_t)EOFF[et] * H,
                                             amax + (size_t)DOFF[et] * H);
        }
        // pass 2: exp + denominators
        for (int et = 0; et < 4; et++) {
            dim3 grid((NEh[et] * H + 255) / 256);
            edge_exp_kernel<<<grid, 256>>>(edst[et], NEh[et],
                                           amax + (size_t)DOFF[et] * H,
                                           alpha + (size_t)EOFF[et] * H,
                                           den + (size_t)DOFF[et] * H);
        }
        // pass 3: weighted aggregation
        for (int et = 0; et < 4; et++) {
            int di = EDST[et];
            dim3 grid((NEh[et] + 7) / 8);
            edge_msg_kernel<<<grid, 256>>>(vet + (size_t)KOFF[et] * C,
                                           esrc[et], edst[et], NEh[et],
                                           alpha + (size_t)EOFF[et] * H,
                                           den + (size_t)DOFF[et] * H,
                                           agg + (size_t)XOFF[di] * C);
        }
        // gelu
        {
            dim3 grid((NTOT * 32 + 255) / 256);
            finalize_gelu<<<grid, 256>>>(agg, gbuf, NTOT);
        }
        // attention output projection + skip + relu (in place on xs)
        for (int i = 0; i < 3; i++) {
            dim3 grid((NNh[i] + 63) / 64);
            gemm_k128<128, 2><<<grid, 256>>>(gbuf + (size_t)XOFF[i] * C,
                                             aw + (size_t)(l * 3 + i) * C * C,
                                             ab + (l * 3 + i) * C,
                                             xs + (size_t)XOFF[i] * C,
                                             NNh[i],
                                             xs + (size_t)XOFF[i] * C,
                                             skip + l * 3 + i);
        }
    }

    // final output projection: [N,128] @ [128,64]
    for (int i = 0; i < 3; i++) {
        dim3 grid((NNh[i] + 127) / 128);
        gemm_k128<64, 0><<<grid, 256>>>(xs + (size_t)XOFF[i] * C,
                                        out_w, out_b,
                                        out + (size_t)XOFF[i] * OUTC,
                                        NNh[i], nullptr, nullptr);
    }
}

// round 2
// speedup vs baseline: 1.2230x; 1.2230x over previous
#include <cuda_runtime.h>
#include <cuda_bf16.h>
#include <cstdint>

// ---------------- problem constants ----------------
#define C 128
#define H 8
#define DD 16
#define OUTC 64
#define NLAYER 2

static const int NNh[3]  = {30000, 60000, 6000};
static const int XOFF[3] = {0, 30000, 90000};
#define NTOT 96000
static const int NEh[4]  = {200000, 300000, 200000, 100000};
static const int EOFF[4] = {0, 200000, 500000, 700000};
#define ETOT 800000
static const int ESRC[4] = {0, 1, 1, 2};
static const int EDST[4] = {1, 1, 2, 0};
static const int KOFF[4] = {0, 30000, 90000, 150000};
#define KETROWS 156000
static const int DOFF[4] = {0, 60000, 120000, 126000};
#define DROWS 156000

// ---------------- scratch (device globals; no allocation allowed) ----------------
__device__ float    g_xs   [NTOT * C];
__device__ float    g_q    [NTOT * C];
__device__ float    g_agg  [NTOT * C];
__device__ float    g_ket  [KETROWS * C];
__device__ float    g_vet  [KETROWS * C];
__device__ float    g_alpha[ETOT * H];
__device__ float    g_den  [DROWS * H];
__device__ unsigned g_amax [DROWS * H];
__device__ float    g_kwc  [NLAYER * 4 * C * C];
__device__ float    g_vwc  [NLAYER * 4 * C * C];
__device__ float    g_kbc  [NLAYER * 4 * C];
__device__ float    g_vbc  [NLAYER * 4 * C];

// ---------------- helpers ----------------
__device__ __forceinline__ unsigned fenc(float f) {
    unsigned u = __float_as_uint(f);
    return (u & 0x80000000u) ? ~u : (u | 0x80000000u);
}
__device__ __forceinline__ float fdec(unsigned u) {
    return (u & 0x80000000u) ? __uint_as_float(u ^ 0x80000000u) : __uint_as_float(~u);
}
__device__ __forceinline__ float gelu_tanh(float x) {
    float x3 = x * x * x;
    return 0.5f * x * (1.0f + tanhf(0.7978845608028654f * (x + 0.044715f * x3)));
}
__device__ __forceinline__ void tf32_split(float x, uint32_t& hi, uint32_t& lo) {
    asm("cvt.rna.tf32.f32 %0, %1;" : "=r"(hi) : "f"(x));
    float r = x - __uint_as_float(hi);
    asm("cvt.rna.tf32.f32 %0, %1;" : "=r"(lo) : "f"(r));
}
__device__ __forceinline__ void mma_tf32(float* c, const uint32_t a[4], uint32_t b0, uint32_t b1) {
    asm volatile("mma.sync.aligned.m16n8k8.row.col.f32.tf32.tf32.f32 "
                 "{%0,%1,%2,%3}, {%4,%5,%6,%7}, {%8,%9}, {%0,%1,%2,%3};"
                 : "+f"(c[0]), "+f"(c[1]), "+f"(c[2]), "+f"(c[3])
                 : "r"(a[0]), "r"(a[1]), "r"(a[2]), "r"(a[3]), "r"(b0), "r"(b1));
}

// ---------------- combined K/V weights (fold a_rel / m_rel into kw / vw) ----------------
__global__ void wcomb_kernel(const float* __restrict__ kw, const float* __restrict__ kb,
                             const float* __restrict__ vw, const float* __restrict__ vb,
                             const float* __restrict__ a_rel, const float* __restrict__ m_rel)
{
    int b  = blockIdx.x;          // 0..7 == l*4+et
    int l  = b >> 2, et = b & 3;
    int si = (et == 0) ? 0 : ((et == 3) ? 2 : 1);
    const float* KW = kw + (size_t)(l * 3 + si) * C * C;
    const float* VW = vw + (size_t)(l * 3 + si) * C * C;
    const float* KB = kb + (size_t)(l * 3 + si) * C;
    const float* VB = vb + (size_t)(l * 3 + si) * C;
    const float* AR = a_rel + (size_t)b * H * DD * DD;
    const float* MR = m_rel + (size_t)b * H * DD * DD;
    float* KWC = g_kwc + (size_t)b * C * C;
    float* VWC = g_vwc + (size_t)b * C * C;

    for (int idx = threadIdx.x; idx < C * C; idx += blockDim.x) {
        int c = idx >> 7, hf = idx & 127, h = hf >> 4, f = hf & 15;
        float sk = 0.f, sv = 0.f;
        #pragma unroll
        for (int d = 0; d < DD; d++) {
            sk += KW[c * C + h * DD + d] * AR[(h * DD + d) * DD + f];
            sv += VW[c * C + h * DD + d] * MR[(h * DD + d) * DD + f];
        }
        KWC[idx] = sk; VWC[idx] = sv;
    }
    if (threadIdx.x < C) {
        int hf = threadIdx.x, h = hf >> 4, f = hf & 15;
        float sk = 0.f, sv = 0.f;
        #pragma unroll
        for (int d = 0; d < DD; d++) {
            sk += KB[h * DD + d] * AR[(h * DD + d) * DD + f];
            sv += VB[h * DD + d] * MR[(h * DD + d) * DD + f];
        }
        g_kbc[b * C + hf] = sk; g_vbc[b * C + hf] = sv;
    }
}

// ---------------- multi-job 3xTF32 tensor-core GEMM: Out[M,128] = A[M,128] @ W[128,128] ----------------
// epi bits: 0x1 relu, 0x2 skip-gate (requires skipx/skipv), 0x4 gelu applied to A on load
struct GemmJob {
    const float *A, *W, *bias;
    float *Out;
    const float *skipx, *skipv;
    int M, blk0, epi;
    int _pad;
};
struct Jobs11 { GemmJob j[11]; };

#define AS_STRIDE 68
#define BS_STRIDE 136
#define GEMM_SMEM ((128 * AS_STRIDE + 64 * BS_STRIDE) * 4)

__global__ void __launch_bounds__(256)
gemm_tf32_jobs(Jobs11 jobs, int njobs)
{
    extern __shared__ float sm[];
    float* As = sm;                    // [128][AS_STRIDE], local k cols 0..63
    float* Bs = sm + 128 * AS_STRIDE;  // [64][BS_STRIDE]

    int bid = blockIdx.x;
    int j = 0;
    while (j + 1 < njobs && bid >= jobs.j[j + 1].blk0) j++;
    const GemmJob& J = jobs.j[j];

    int tid  = threadIdx.x;
    int lane = tid & 31, warp = tid >> 5;
    int wm = warp & 1, wn = warp >> 1;        // 2 x 4 warp grid, warp tile 64x32
    int g = lane >> 2, t = lane & 3;
    int row0 = (bid - J.blk0) * 128;
    bool doGelu = (J.epi & 4) != 0;

    float acc[4][4][4];
    #pragma unroll
    for (int a = 0; a < 4; a++)
        #pragma unroll
        for (int b = 0; b < 4; b++)
            #pragma unroll
            for (int c = 0; c < 4; c++) acc[a][b][c] = 0.f;

    #pragma unroll
    for (int ch = 0; ch < 2; ch++) {
        int k0 = ch * 64;
        // A tile: 128 rows x 64 k
        {
            int r  = tid >> 4;            // 0..15
            int c4 = (tid & 15) * 4;      // 0..60
            #pragma unroll
            for (int p = 0; p < 8; p++) {
                int rr = r + p * 16;
                int gr = row0 + rr;
                float4 v = make_float4(0.f, 0.f, 0.f, 0.f);
                if (gr < J.M) v = *(const float4*)(J.A + (size_t)gr * 128 + k0 + c4);
                if (doGelu) {
                    v.x = gelu_tanh(v.x); v.y = gelu_tanh(v.y);
                    v.z = gelu_tanh(v.z); v.w = gelu_tanh(v.w);
                }
                *(float4*)(As + rr * AS_STRIDE + c4) = v;
            }
        }
        // B tile: 64 k x 128 n
        {
            int kr = tid >> 5;            // 0..7
            int c4 = (tid & 31) * 4;      // 0..124
            #pragma unroll
            for (int p = 0; p < 8; p++) {
                int kk = kr + p * 8;
                float4 v = *(const float4*)(J.W + (size_t)(k0 + kk) * 128 + c4);
                *(float4*)(Bs + kk * BS_STRIDE + c4) = v;
            }
        }
        __syncthreads();

        #pragma unroll
        for (int kk = 0; kk < 8; kk++) {
            int k = kk * 8;
            uint32_t ahi[4][4], alo[4][4];
            #pragma unroll
            for (int mf = 0; mf < 4; mf++) {
                int rm = wm * 64 + mf * 16;
                float x0 = As[(rm + g)     * AS_STRIDE + k + t];
                float x1 = As[(rm + g + 8) * AS_STRIDE + k + t];
                float x2 = As[(rm + g)     * AS_STRIDE + k + t + 4];
                float x3 = As[(rm + g + 8) * AS_STRIDE + k + t + 4];
                tf32_split(x0, ahi[mf][0], alo[mf][0]);
                tf32_split(x1, ahi[mf][1], alo[mf][1]);
                tf32_split(x2, ahi[mf][2], alo[mf][2]);
                tf32_split(x3, ahi[mf][3], alo[mf][3]);
            }
            #pragma unroll
            for (int nf = 0; nf < 4; nf++) {
                int cn = wn * 32 + nf * 8 + g;
                float b0f = Bs[(k + t)     * BS_STRIDE + cn];
                float b1f = Bs[(k + t + 4) * BS_STRIDE + cn];
                uint32_t bh0, bl0, bh1, bl1;
                tf32_split(b0f, bh0, bl0);
                tf32_split(b1f, bh1, bl1);
                #pragma unroll
                for (int mf = 0; mf < 4; mf++) {
                    mma_tf32(acc[mf][nf], ahi[mf], bh0, bh1);
                    mma_tf32(acc[mf][nf], alo[mf], bh0, bh1);
                    mma_tf32(acc[mf][nf], ahi[mf], bl0, bl1);
                }
            }
        }
        __syncthreads();
    }

    // epilogue
    float beta = 1.f, omb = 0.f;
    if (J.epi & 2) {
        float sv = *J.skipv;
        beta = 1.f / (1.f + __expf(-sv));
        omb  = 1.f - beta;
    }
    bool relu = (J.epi & 1) || (J.epi & 2);

    #pragma unroll
    for (int nf = 0; nf < 4; nf++) {
        int col = wn * 32 + nf * 8 + t * 2;
        float bc0 = J.bias[col], bc1 = J.bias[col + 1];
        #pragma unroll
        for (int mf = 0; mf < 4; mf++) {
            int r0 = row0 + wm * 64 + mf * 16 + g;
            int r1 = r0 + 8;
            float o00 = acc[mf][nf][0] + bc0, o01 = acc[mf][nf][1] + bc1;
            float o10 = acc[mf][nf][2] + bc0, o11 = acc[mf][nf][3] + bc1;
            if (J.epi & 2) {
                if (r0 < J.M) {
                    float2 s = *(const float2*)(J.skipx + (size_t)r0 * 128 + col);
                    o00 = beta * o00 + omb * s.x;
                    o01 = beta * o01 + omb * s.y;
                }
                if (r1 < J.M) {
                    float2 s = *(const float2*)(J.skipx + (size_t)r1 * 128 + col);
                    o10 = beta * o10 + omb * s.x;
                    o11 = beta * o11 + omb * s.y;
                }
            }
            if (relu) {
                o00 = fmaxf(o00, 0.f); o01 = fmaxf(o01, 0.f);
                o10 = fmaxf(o10, 0.f); o11 = fmaxf(o11, 0.f);
            }
            if (r0 < J.M) *(float2*)(J.Out + (size_t)r0 * 128 + col) = make_float2(o00, o01);
            if (r1 < J.M) *(float2*)(J.Out + (size_t)r1 * 128 + col) = make_float2(o10, o11);
        }
    }
}

// ---------------- scalar GEMM for the final [128 x 64] projection ----------------
__global__ void __launch_bounds__(256)
gemm_out64(const float* __restrict__ A, const float* __restrict__ W,
           const float* __restrict__ bias, float* __restrict__ Out, int M)
{
    constexpr int BN = 64, CT = BN / 4, BM = (256 / CT) * 8, BK = 32, AP = BM + 4;
    __shared__ float As[BK][AP];
    __shared__ float Bs[BK][BN];

    int tid = threadIdx.x;
    int row0 = blockIdx.x * BM;
    int trow = (tid / CT) * 8;
    int tcol = (tid % CT) * 4;

    float acc[8][4];
    #pragma unroll
    for (int r = 0; r < 8; r++)
        #pragma unroll
        for (int c = 0; c < 4; c++) acc[r][c] = 0.f;

    for (int k0 = 0; k0 < 128; k0 += BK) {
        #pragma unroll
        for (int i = 0; i < (BM * 8) / 256; ++i) {
            int id = tid + i * 256;
            int r = id >> 3, kq = id & 7;
            float4 v = make_float4(0.f, 0.f, 0.f, 0.f);
            int gr = row0 + r;
            if (gr < M) v = *(const float4*)(A + (size_t)gr * 128 + k0 + kq * 4);
            As[kq * 4 + 0][r] = v.x; As[kq * 4 + 1][r] = v.y;
            As[kq * 4 + 2][r] = v.z; As[kq * 4 + 3][r] = v.w;
        }
        #pragma unroll
        for (int i = 0; i < (8 * BN) / 256; ++i) {
            int id = tid + i * 256;
            int kr = id / CT, c4 = (id % CT) * 4;
            *(float4*)&Bs[kr][c4] = *(const float4*)(W + (size_t)(k0 + kr) * BN + c4);
        }
        __syncthreads();
        #pragma unroll
        for (int k = 0; k < BK; ++k) {
            float4 b = *(float4*)&Bs[k][tcol];
            #pragma unroll
            for (int r = 0; r < 8; r++) {
                float a = As[k][trow + r];
                acc[r][0] += a * b.x; acc[r][1] += a * b.y;
                acc[r][2] += a * b.z; acc[r][3] += a * b.w;
            }
        }
        __syncthreads();
    }
    float b0 = bias[tcol], b1 = bias[tcol + 1], b2 = bias[tcol + 2], b3 = bias[tcol + 3];
    #pragma unroll
    for (int r = 0; r < 8; r++) {
        int gr = row0 + trow + r;
        if (gr >= M) break;
        float4 o = make_float4(acc[r][0] + b0, acc[r][1] + b1, acc[r][2] + b2, acc[r][3] + b3);
        *(float4*)(Out + (size_t)gr * BN + tcol) = o;
    }
}

// ---------------- edge pass 1: raw attention logits + segment max ----------------
__global__ void __launch_bounds__(256)
edge_alpha_kernel(const float* __restrict__ qb, const float* __restrict__ ketb,
                  const int* __restrict__ src, const int* __restrict__ dst, int E,
                  const float* __restrict__ prel,
                  float* __restrict__ alpha, unsigned* __restrict__ amax)
{
    int e = blockIdx.x * 8 + (threadIdx.x >> 5);
    if (e >= E) return;
    int lane = threadIdx.x & 31;
    int s = src[e], d = dst[e];
    float4 qv = ((const float4*)(qb  + (size_t)d * 128))[lane];
    float4 kv = ((const float4*)(ketb + (size_t)s * 128))[lane];
    float p = qv.x * kv.x + qv.y * kv.y + qv.z * kv.z + qv.w * kv.w;
    p += __shfl_xor_sync(0xffffffffu, p, 1);
    p += __shfl_xor_sync(0xffffffffu, p, 2);
    int h = lane >> 2;
    if ((lane & 3) == 0) {
        float a = p * 0.25f * prel[h];
        alpha[(size_t)e * H + h] = a;
        atomicMax(&amax[(size_t)d * H + h], fenc(a));
    }
}

// ---------------- edge pass 2: exp + segment denominator ----------------
__global__ void __launch_bounds__(256)
edge_exp_kernel(const int* __restrict__ dst, int E,
                const unsigned* __restrict__ amax,
                float* __restrict__ alpha, float* __restrict__ den)
{
    int i = blockIdx.x * 256 + threadIdx.x;
    if (i >= E * H) return;
    int e = i >> 3, h = i & 7;
    int d = dst[e];
    float m = fdec(amax[(size_t)d * H + h]);
    float ex = __expf(alpha[i] - m);
    alpha[i] = ex;
    atomicAdd(&den[(size_t)d * H + h], ex);
}

// ---------------- edge pass 3: weighted message aggregation ----------------
__global__ void __launch_bounds__(256)
edge_msg_kernel(const float* __restrict__ vetb,
                const int* __restrict__ src, const int* __restrict__ dst, int E,
                const float* __restrict__ alpha, const float* __restrict__ den,
                float* __restrict__ agg)
{
    int e = blockIdx.x * 8 + (threadIdx.x >> 5);
    if (e >= E) return;
    int lane = threadIdx.x & 31;
    int s = src[e], d = dst[e];
    int h = lane >> 2;
    float ex = alpha[(size_t)e * H + h];
    float dn = den[(size_t)d * H + h];
    float w  = ex / (dn + 1e-16f);
    float4 v = ((const float4*)(vetb + (size_t)s * 128))[lane];
    v.x *= w; v.y *= w; v.z *= w; v.w *= w;
    atomicAdd((float4*)(agg + (size_t)d * 128 + lane * 4), v);
}

// ---------------- host orchestration ----------------
static inline int nb128(int m) { return (m + 127) / 128; }

extern "C" void kernel_launch(void* const* d_in, const int* in_sizes, int n_in,
                              void* d_out, int out_size)
{
    const float* x_in[3] = {(const float*)d_in[0], (const float*)d_in[1], (const float*)d_in[2]};
    const int* esrc[4] = {(const int*)d_in[3], (const int*)d_in[5], (const int*)d_in[7], (const int*)d_in[9]};
    const int* edst[4] = {(const int*)d_in[4], (const int*)d_in[6], (const int*)d_in[8], (const int*)d_in[10]};
    const float* lin_w = (const float*)d_in[11];
    const float* lin_b = (const float*)d_in[12];
    const float* kw    = (const float*)d_in[13];
    const float* qw    = (const float*)d_in[14];
    const float* vw    = (const float*)d_in[15];
    const float* aw    = (const float*)d_in[16];
    const float* kb    = (const float*)d_in[17];
    const float* qb    = (const float*)d_in[18];
    const float* vb    = (const float*)d_in[19];
    const float* ab    = (const float*)d_in[20];
    const float* a_rel = (const float*)d_in[21];
    const float* m_rel = (const float*)d_in[22];
    const float* p_rel = (const float*)d_in[23];
    const float* skip  = (const float*)d_in[24];
    const float* out_w = (const float*)d_in[25];
    const float* out_b = (const float*)d_in[26];
    float* out = (float*)d_out;

    float *xs, *q, *agg, *ket, *vet, *alpha, *den, *kwc, *vwc, *kbc, *vbc;
    unsigned* amax;
    cudaGetSymbolAddress((void**)&xs,   g_xs);
    cudaGetSymbolAddress((void**)&q,    g_q);
    cudaGetSymbolAddress((void**)&agg,  g_agg);
    cudaGetSymbolAddress((void**)&ket,  g_ket);
    cudaGetSymbolAddress((void**)&vet,  g_vet);
    cudaGetSymbolAddress((void**)&alpha,g_alpha);
    cudaGetSymbolAddress((void**)&den,  g_den);
    cudaGetSymbolAddress((void**)&amax, g_amax);
    cudaGetSymbolAddress((void**)&kwc,  g_kwc);
    cudaGetSymbolAddress((void**)&vwc,  g_vwc);
    cudaGetSymbolAddress((void**)&kbc,  g_kbc);
    cudaGetSymbolAddress((void**)&vbc,  g_vbc);

    static bool attr_done = false;
    if (!attr_done) {
        cudaFuncSetAttribute(gemm_tf32_jobs, cudaFuncAttributeMaxDynamicSharedMemorySize, GEMM_SMEM);
        attr_done = true;
    }

    wcomb_kernel<<<8, 256>>>(kw, kb, vw, vb, a_rel, m_rel);

    // ---- input linear + relu (3 jobs, one launch) ----
    {
        Jobs11 js{}; int nj = 0, blk = 0;
        for (int i = 0; i < 3; i++) {
            GemmJob& J = js.j[nj++];
            J.A = x_in[i]; J.W = lin_w + (size_t)i * C * C; J.bias = lin_b + i * C;
            J.Out = xs + (size_t)XOFF[i] * C; J.M = NNh[i]; J.blk0 = blk; J.epi = 1;
            J.skipx = nullptr; J.skipv = nullptr;
            blk += nb128(NNh[i]);
        }
        gemm_tf32_jobs<<<blk, 256, GEMM_SMEM>>>(js, nj);
    }

    for (int l = 0; l < NLAYER; l++) {
        // ---- Q + K_et + V_et projections (11 jobs, one launch) ----
        {
            Jobs11 js{}; int nj = 0, blk = 0;
            for (int i = 0; i < 3; i++) {
                GemmJob& J = js.j[nj++];
                J.A = xs + (size_t)XOFF[i] * C;
                J.W = qw + (size_t)(l * 3 + i) * C * C;
                J.bias = qb + (l * 3 + i) * C;
                J.Out = q + (size_t)XOFF[i] * C;
                J.M = NNh[i]; J.blk0 = blk; J.epi = 0;
                blk += nb128(NNh[i]);
            }
            for (int et = 0; et < 4; et++) {
                int si = ESRC[et];
                {
                    GemmJob& J = js.j[nj++];
                    J.A = xs + (size_t)XOFF[si] * C;
                    J.W = kwc + (size_t)(l * 4 + et) * C * C;
                    J.bias = kbc + (l * 4 + et) * C;
                    J.Out = ket + (size_t)KOFF[et] * C;
                    J.M = NNh[si]; J.blk0 = blk; J.epi = 0;
                    blk += nb128(NNh[si]);
                }
                {
                    GemmJob& J = js.j[nj++];
                    J.A = xs + (size_t)XOFF[si] * C;
                    J.W = vwc + (size_t)(l * 4 + et) * C * C;
                    J.bias = vbc + (l * 4 + et) * C;
                    J.Out = vet + (size_t)KOFF[et] * C;
                    J.M = NNh[si]; J.blk0 = blk; J.epi = 0;
                    blk += nb128(NNh[si]);
                }
            }
            gemm_tf32_jobs<<<blk, 256, GEMM_SMEM>>>(js, nj);
        }

        cudaMemsetAsync(agg,  0, (size_t)NTOT * C * sizeof(float));
        cudaMemsetAsync(den,  0, (size_t)DROWS * H * sizeof(float));
        cudaMemsetAsync(amax, 0, (size_t)DROWS * H * sizeof(unsigned));

        for (int et = 0; et < 4; et++) {
            int di = EDST[et];
            dim3 grid((NEh[et] + 7) / 8);
            edge_alpha_kernel<<<grid, 256>>>(q + (size_t)XOFF[di] * C,
                                             ket + (size_t)KOFF[et] * C,
                                             esrc[et], edst[et], NEh[et],
                                             p_rel + (l * 4 + et) * H,
                                             alpha + (size_t)EOFF[et] * H,
                                             amax + (size_t)DOFF[et] * H);
        }
        for (int et = 0; et < 4; et++) {
            dim3 grid((NEh[et] * H + 255) / 256);
            edge_exp_kernel<<<grid, 256>>>(edst[et], NEh[et],
                                           amax + (size_t)DOFF[et] * H,
                                           alpha + (size_t)EOFF[et] * H,
                                           den + (size_t)DOFF[et] * H);
        }
        for (int et = 0; et < 4; et++) {
            int di = EDST[et];
            dim3 grid((NEh[et] + 7) / 8);
            edge_msg_kernel<<<grid, 256>>>(vet + (size_t)KOFF[et] * C,
                                           esrc[et], edst[et], NEh[et],
                                           alpha + (size_t)EOFF[et] * H,
                                           den + (size_t)DOFF[et] * H,
                                           agg + (size_t)XOFF[di] * C);
        }

        // ---- attn-out projection, gelu fused on A, skip-gate + relu epilogue ----
        {
            Jobs11 js{}; int nj = 0, blk = 0;
            for (int i = 0; i < 3; i++) {
                GemmJob& J = js.j[nj++];
                J.A = agg + (size_t)XOFF[i] * C;
                J.W = aw + (size_t)(l * 3 + i) * C * C;
                J.bias = ab + (l * 3 + i) * C;
                J.Out = xs + (size_t)XOFF[i] * C;
                J.skipx = xs + (size_t)XOFF[i] * C;
                J.skipv = skip + l * 3 + i;
                J.M = NNh[i]; J.blk0 = blk; J.epi = 2 | 4;
                blk += nb128(NNh[i]);
            }
            gemm_tf32_jobs<<<blk, 256, GEMM_SMEM>>>(js, nj);
        }
    }

    // ---- final output projection [N,128] @ [128,64] ----
    for (int i = 0; i < 3; i++) {
        dim3 grid((NNh[i] + 127) / 128);
        gemm_out64<<<grid, 256>>>(xs + (size_t)XOFF[i] * C, out_w, out_b,
                                  out + (size_t)XOFF[i] * OUTC, NNh[i]);
    }
}

// round 3
// speedup vs baseline: 1.4963x; 1.2235x over previous
#include <cuda_runtime.h>
#include <cuda_bf16.h>
#include <cstdint>

// ---------------- problem constants ----------------
#define C 128
#define H 8
#define DD 16
#define OUTC 64
#define NLAYER 2

static const int NNh[3]  = {30000, 60000, 6000};
static const int XOFF[3] = {0, 30000, 90000};
#define NTOT 96000
static const int NEh[4]  = {200000, 300000, 200000, 100000};
#define ETOT 800000
static const int ESRC[4] = {0, 1, 1, 2};
// dst types per et: 1,1,2,0
// CSR stat segments per et, sized by dst-type node count:
#define DOFF0 0
#define DOFF1 60000
#define DOFF2 120000
#define DOFF3 126000
#define DROWS 156000
// ket/vet segments per et (sized by src-type node count)
#define KOFF0 0
#define KOFF1 30000
#define KOFF2 90000
#define KOFF3 150000
#define KETROWS 156000

// ---------------- scratch (device globals; no allocation allowed) ----------------
__device__ float    g_xs   [NTOT * C];
__device__ float    g_q    [NTOT * C];
__device__ float    g_agg  [NTOT * C];
__device__ float    g_ket  [KETROWS * C];
__device__ float    g_vet  [KETROWS * C];
__device__ float    g_alpha[ETOT * H];
__device__ int      g_cnt  [DROWS];
__device__ int      g_off  [DROWS + 1];
__device__ int      g_woff [DROWS];
__device__ int      g_part [256];
__device__ int      g_ssrc [ETOT];
__device__ float    g_kwc  [NLAYER * 4 * C * C];
__device__ float    g_vwc  [NLAYER * 4 * C * C];
__device__ float    g_kbc  [NLAYER * 4 * C];
__device__ float    g_vbc  [NLAYER * 4 * C];

// ---------------- helpers ----------------
__device__ __forceinline__ float gelu_tanh(float x) {
    float x3 = x * x * x;
    return 0.5f * x * (1.0f + tanhf(0.7978845608028654f * (x + 0.044715f * x3)));
}
__device__ __forceinline__ void tf32_split(float x, uint32_t& hi, uint32_t& lo) {
    asm("cvt.rna.tf32.f32 %0, %1;" : "=r"(hi) : "f"(x));
    float r = x - __uint_as_float(hi);
    asm("cvt.rna.tf32.f32 %0, %1;" : "=r"(lo) : "f"(r));
}
__device__ __forceinline__ void mma_tf32(float* c, const uint32_t a[4], uint32_t b0, uint32_t b1) {
    asm volatile("mma.sync.aligned.m16n8k8.row.col.f32.tf32.tf32.f32 "
                 "{%0,%1,%2,%3}, {%4,%5,%6,%7}, {%8,%9}, {%0,%1,%2,%3};"
                 : "+f"(c[0]), "+f"(c[1]), "+f"(c[2]), "+f"(c[3])
                 : "r"(a[0]), "r"(a[1]), "r"(a[2]), "r"(a[3]), "r"(b0), "r"(b1));
}

// ---------------- combined K/V weights (fold a_rel / m_rel into kw / vw) ----------------
__global__ void wcomb_kernel(const float* __restrict__ kw, const float* __restrict__ kb,
                             const float* __restrict__ vw, const float* __restrict__ vb,
                             const float* __restrict__ a_rel, const float* __restrict__ m_rel)
{
    int b  = blockIdx.x;          // 0..7 == l*4+et
    int l  = b >> 2, et = b & 3;
    int si = (et == 0) ? 0 : ((et == 3) ? 2 : 1);
    const float* KW = kw + (size_t)(l * 3 + si) * C * C;
    const float* VW = vw + (size_t)(l * 3 + si) * C * C;
    const float* KB = kb + (size_t)(l * 3 + si) * C;
    const float* VB = vb + (size_t)(l * 3 + si) * C;
    const float* AR = a_rel + (size_t)b * H * DD * DD;
    const float* MR = m_rel + (size_t)b * H * DD * DD;
    float* KWC = g_kwc + (size_t)b * C * C;
    float* VWC = g_vwc + (size_t)b * C * C;

    for (int idx = threadIdx.x; idx < C * C; idx += blockDim.x) {
        int c = idx >> 7, hf = idx & 127, h = hf >> 4, f = hf & 15;
        float sk = 0.f, sv = 0.f;
        #pragma unroll
        for (int d = 0; d < DD; d++) {
            sk += KW[c * C + h * DD + d] * AR[(h * DD + d) * DD + f];
            sv += VW[c * C + h * DD + d] * MR[(h * DD + d) * DD + f];
        }
        KWC[idx] = sk; VWC[idx] = sv;
    }
    if (threadIdx.x < C) {
        int hf = threadIdx.x, h = hf >> 4, f = hf & 15;
        float sk = 0.f, sv = 0.f;
        #pragma unroll
        for (int d = 0; d < DD; d++) {
            sk += KB[h * DD + d] * AR[(h * DD + d) * DD + f];
            sv += VB[h * DD + d] * MR[(h * DD + d) * DD + f];
        }
        g_kbc[b * C + hf] = sk; g_vbc[b * C + hf] = sv;
    }
}

// ---------------- CSR build: histogram -> scan -> scatter ----------------
__global__ void hist_kernel(const int* __restrict__ dst, int E, int* __restrict__ cnt)
{
    int i = blockIdx.x * 256 + threadIdx.x;
    if (i < E) atomicAdd(&cnt[dst[i]], 1);
}

__global__ void scan_block(const int* __restrict__ cnt, int* __restrict__ off, int* __restrict__ part)
{
    __shared__ int sm[1024];
    int tid = threadIdx.x;
    int i = blockIdx.x * 1024 + tid;
    int v = (i < DROWS) ? cnt[i] : 0;
    sm[tid] = v;
    __syncthreads();
    #pragma unroll
    for (int ofs = 1; ofs < 1024; ofs <<= 1) {
        int t = (tid >= ofs) ? sm[tid - ofs] : 0;
        __syncthreads();
        sm[tid] += t;
        __syncthreads();
    }
    if (i < DROWS) off[i] = sm[tid] - v;    // exclusive within block
    if (tid == 1023) part[blockIdx.x] = sm[1023];
}

__global__ void scan_part(int* part, int nb)
{
    if (threadIdx.x == 0 && blockIdx.x == 0) {
        int s = 0;
        for (int i = 0; i < nb; i++) { int t = part[i]; part[i] = s; s += t; }
    }
}

__global__ void scan_add(int* __restrict__ off, const int* __restrict__ part,
                         int* __restrict__ woff)
{
    int i = blockIdx.x * 256 + threadIdx.x;
    if (i < DROWS) {
        int o = off[i] + part[i >> 10];
        off[i] = o;
        woff[i] = o;
    }
    if (i == DROWS) off[DROWS] = ETOT;
}

__global__ void scatter_kernel(const int* __restrict__ src, const int* __restrict__ dst,
                               int E, int* __restrict__ woffb, int* __restrict__ ssrc)
{
    int i = blockIdx.x * 256 + threadIdx.x;
    if (i < E) {
        int p = atomicAdd(&woffb[dst[i]], 1);
        ssrc[p] = src[i];
    }
}

// ---------------- fused attention: one warp per destination node, no atomics ----------------
__device__ __forceinline__ void attn_sweep(
    const float4 q4, int lane, int h,
    int beg, int end, int koff,
    const float* __restrict__ ket, const float* __restrict__ vet,
    float* __restrict__ alpha, float ps, float4& accOut)
{
    // sweep 1: logits + per-head max
    float m = -1e30f;
    int s = (beg < end) ? __ldg(&g_ssrc[beg]) : 0;
    for (int p = beg; p < end; p++) {
        int sn = (p + 1 < end) ? __ldg(&g_ssrc[p + 1]) : 0;
        float4 k4 = ((const float4*)(ket + (size_t)(koff + s) * 128))[lane];
        float dt = q4.x * k4.x + q4.y * k4.y + q4.z * k4.z + q4.w * k4.w;
        dt += __shfl_xor_sync(0xffffffffu, dt, 1);
        dt += __shfl_xor_sync(0xffffffffu, dt, 2);
        float a = dt * ps;
        alpha[(size_t)p * H + h] = a;        // all 4 lanes write same value (benign)
        m = fmaxf(m, a);
        s = sn;
    }
    // sweep 2: exp, denominator, weighted accumulation
    float den = 0.f;
    float4 acc = make_float4(0.f, 0.f, 0.f, 0.f);
    s = (beg < end) ? __ldg(&g_ssrc[beg]) : 0;
    for (int p = beg; p < end; p++) {
        int sn = (p + 1 < end) ? __ldg(&g_ssrc[p + 1]) : 0;
        float a = alpha[(size_t)p * H + h];
        float ex = __expf(a - m);
        den += ex;
        float4 v4 = ((const float4*)(vet + (size_t)(koff + s) * 128))[lane];
        acc.x += ex * v4.x; acc.y += ex * v4.y;
        acc.z += ex * v4.z; acc.w += ex * v4.w;
        s = sn;
    }
    float w = 1.f / (den + 1e-16f);
    accOut.x += acc.x * w; accOut.y += acc.y * w;
    accOut.z += acc.z * w; accOut.w += acc.w * w;
}

__global__ void __launch_bounds__(256)
attn_fused(const float* __restrict__ q, const float* __restrict__ ket,
           const float* __restrict__ vet, const int* __restrict__ off,
           float* __restrict__ alpha, float* __restrict__ agg,
           const float* __restrict__ p_rel, int layer)
{
    int w = (blockIdx.x * 256 + threadIdx.x) >> 5;
    if (w >= NTOT) return;
    int lane = threadIdx.x & 31;
    int h = lane >> 2;

    float4 acc = make_float4(0.f, 0.f, 0.f, 0.f);
    int node;   // global node row in xs/q/agg space

    if (w < 60000) {
        // road (type 1): receives et0 and et1
        int d = w;
        node = 30000 + d;
        float4 q4 = ((const float4*)(q + (size_t)node * 128))[lane];
        {
            float ps = p_rel[(layer * 4 + 0) * H + h] * 0.25f;
            attn_sweep(q4, lane, h, off[DOFF0 + d], off[DOFF0 + d + 1],
                       KOFF0, ket, vet, alpha, ps, acc);
        }
        {
            float ps = p_rel[(layer * 4 + 1) * H + h] * 0.25f;
            attn_sweep(q4, lane, h, off[DOFF1 + d], off[DOFF1 + d + 1],
                       KOFF1, ket, vet, alpha, ps, acc);
        }
    } else if (w < 90000) {
        // poi (type 0): receives et3
        int d = w - 60000;
        node = d;
        float4 q4 = ((const float4*)(q + (size_t)node * 128))[lane];
        float ps = p_rel[(layer * 4 + 3) * H + h] * 0.25f;
        attn_sweep(q4, lane, h, off[DOFF3 + d], off[DOFF3 + d + 1],
                   KOFF3, ket, vet, alpha, ps, acc);
    } else {
        // region (type 2): receives et2
        int d = w - 90000;
        node = 90000 + d;
        float4 q4 = ((const float4*)(q + (size_t)node * 128))[lane];
        float ps = p_rel[(layer * 4 + 2) * H + h] * 0.25f;
        attn_sweep(q4, lane, h, off[DOFF2 + d], off[DOFF2 + d + 1],
                   KOFF2, ket, vet, alpha, ps, acc);
    }
    ((float4*)(agg + (size_t)node * 128))[lane] = acc;
}

// ---------------- multi-job 3xTF32 tensor-core GEMM: Out[M,128] = A[M,128] @ W[128,128] ----------------
// epi bits: 0x1 relu, 0x2 skip-gate (requires skipx/skipv), 0x4 gelu applied to A on load
struct GemmJob {
    const float *A, *W, *bias;
    float *Out;
    const float *skipx, *skipv;
    int M, blk0, epi;
    int _pad;
};
struct Jobs11 { GemmJob j[11]; };

#define AS_STRIDE 68
#define BS_STRIDE 136
#define GEMM_SMEM ((128 * AS_STRIDE + 64 * BS_STRIDE) * 4)

__global__ void __launch_bounds__(256)
gemm_tf32_jobs(Jobs11 jobs, int njobs)
{
    extern __shared__ float sm[];
    float* As = sm;                    // [128][AS_STRIDE], local k cols 0..63
    float* Bs = sm + 128 * AS_STRIDE;  // [64][BS_STRIDE]

    int bid = blockIdx.x;
    int j = 0;
    while (j + 1 < njobs && bid >= jobs.j[j + 1].blk0) j++;
    const GemmJob& J = jobs.j[j];

    int tid  = threadIdx.x;
    int lane = tid & 31, warp = tid >> 5;
    int wm = warp & 1, wn = warp >> 1;        // 2 x 4 warp grid, warp tile 64x32
    int g = lane >> 2, t = lane & 3;
    int row0 = (bid - J.blk0) * 128;
    bool doGelu = (J.epi & 4) != 0;

    float acc[4][4][4];
    #pragma unroll
    for (int a = 0; a < 4; a++)
        #pragma unroll
        for (int b = 0; b < 4; b++)
            #pragma unroll
            for (int c = 0; c < 4; c++) acc[a][b][c] = 0.f;

    #pragma unroll
    for (int ch = 0; ch < 2; ch++) {
        int k0 = ch * 64;
        // A tile: 128 rows x 64 k
        {
            int r  = tid >> 4;            // 0..15
            int c4 = (tid & 15) * 4;      // 0..60
            #pragma unroll
            for (int p = 0; p < 8; p++) {
                int rr = r + p * 16;
                int gr = row0 + rr;
                float4 v = make_float4(0.f, 0.f, 0.f, 0.f);
                if (gr < J.M) v = *(const float4*)(J.A + (size_t)gr * 128 + k0 + c4);
                if (doGelu) {
                    v.x = gelu_tanh(v.x); v.y = gelu_tanh(v.y);
                    v.z = gelu_tanh(v.z); v.w = gelu_tanh(v.w);
                }
                *(float4*)(As + rr * AS_STRIDE + c4) = v;
            }
        }
        // B tile: 64 k x 128 n
        {
            int kr = tid >> 5;            // 0..7
            int c4 = (tid & 31) * 4;      // 0..124
            #pragma unroll
            for (int p = 0; p < 8; p++) {
                int kk = kr + p * 8;
                float4 v = *(const float4*)(J.W + (size_t)(k0 + kk) * 128 + c4);
                *(float4*)(Bs + kk * BS_STRIDE + c4) = v;
            }
        }
        __syncthreads();

        #pragma unroll
        for (int kk = 0; kk < 8; kk++) {
            int k = kk * 8;
            uint32_t ahi[4][4], alo[4][4];
            #pragma unroll
            for (int mf = 0; mf < 4; mf++) {
                int rm = wm * 64 + mf * 16;
                float x0 = As[(rm + g)     * AS_STRIDE + k + t];
                float x1 = As[(rm + g + 8) * AS_STRIDE + k + t];
                float x2 = As[(rm + g)     * AS_STRIDE + k + t + 4];
                float x3 = As[(rm + g + 8) * AS_STRIDE + k + t + 4];
                tf32_split(x0, ahi[mf][0], alo[mf][0]);
                tf32_split(x1, ahi[mf][1], alo[mf][1]);
                tf32_split(x2, ahi[mf][2], alo[mf][2]);
                tf32_split(x3, ahi[mf][3], alo[mf][3]);
            }
            #pragma unroll
            for (int nf = 0; nf < 4; nf++) {
                int cn = wn * 32 + nf * 8 + g;
                float b0f = Bs[(k + t)     * BS_STRIDE + cn];
                float b1f = Bs[(k + t + 4) * BS_STRIDE + cn];
                uint32_t bh0, bl0, bh1, bl1;
                tf32_split(b0f, bh0, bl0);
                tf32_split(b1f, bh1, bl1);
                #pragma unroll
                for (int mf = 0; mf < 4; mf++) {
                    mma_tf32(acc[mf][nf], ahi[mf], bh0, bh1);
                    mma_tf32(acc[mf][nf], alo[mf], bh0, bh1);
                    mma_tf32(acc[mf][nf], ahi[mf], bl0, bl1);
                }
            }
        }
        __syncthreads();
    }

    // epilogue
    float beta = 1.f, omb = 0.f;
    if (J.epi & 2) {
        float sv = *J.skipv;
        beta = 1.f / (1.f + __expf(-sv));
        omb  = 1.f - beta;
    }
    bool relu = (J.epi & 1) || (J.epi & 2);

    #pragma unroll
    for (int nf = 0; nf < 4; nf++) {
        int col = wn * 32 + nf * 8 + t * 2;
        float bc0 = J.bias[col], bc1 = J.bias[col + 1];
        #pragma unroll
        for (int mf = 0; mf < 4; mf++) {
            int r0 = row0 + wm * 64 + mf * 16 + g;
            int r1 = r0 + 8;
            float o00 = acc[mf][nf][0] + bc0, o01 = acc[mf][nf][1] + bc1;
            float o10 = acc[mf][nf][2] + bc0, o11 = acc[mf][nf][3] + bc1;
            if (J.epi & 2) {
                if (r0 < J.M) {
                    float2 s = *(const float2*)(J.skipx + (size_t)r0 * 128 + col);
                    o00 = beta * o00 + omb * s.x;
                    o01 = beta * o01 + omb * s.y;
                }
                if (r1 < J.M) {
                    float2 s = *(const float2*)(J.skipx + (size_t)r1 * 128 + col);
                    o10 = beta * o10 + omb * s.x;
                    o11 = beta * o11 + omb * s.y;
                }
            }
            if (relu) {
                o00 = fmaxf(o00, 0.f); o01 = fmaxf(o01, 0.f);
                o10 = fmaxf(o10, 0.f); o11 = fmaxf(o11, 0.f);
            }
            if (r0 < J.M) *(float2*)(J.Out + (size_t)r0 * 128 + col) = make_float2(o00, o01);
            if (r1 < J.M) *(float2*)(J.Out + (size_t)r1 * 128 + col) = make_float2(o10, o11);
        }
    }
}

// ---------------- scalar GEMM for the final [128 x 64] projection ----------------
__global__ void __launch_bounds__(256)
gemm_out64(const float* __restrict__ A, const float* __restrict__ W,
           const float* __restrict__ bias, float* __restrict__ Out, int M)
{
    constexpr int BN = 64, CT = BN / 4, BM = (256 / CT) * 8, BK = 32, AP = BM + 4;
    __shared__ float As[BK][AP];
    __shared__ float Bs[BK][BN];

    int tid = threadIdx.x;
    int row0 = blockIdx.x * BM;
    int trow = (tid / CT) * 8;
    int tcol = (tid % CT) * 4;

    float acc[8][4];
    #pragma unroll
    for (int r = 0; r < 8; r++)
        #pragma unroll
        for (int c = 0; c < 4; c++) acc[r][c] = 0.f;

    for (int k0 = 0; k0 < 128; k0 += BK) {
        #pragma unroll
        for (int i = 0; i < (BM * 8) / 256; ++i) {
            int id = tid + i * 256;
            int r = id >> 3, kq = id & 7;
            float4 v = make_float4(0.f, 0.f, 0.f, 0.f);
            int gr = row0 + r;
            if (gr < M) v = *(const float4*)(A + (size_t)gr * 128 + k0 + kq * 4);
            As[kq * 4 + 0][r] = v.x; As[kq * 4 + 1][r] = v.y;
            As[kq * 4 + 2][r] = v.z; As[kq * 4 + 3][r] = v.w;
        }
        #pragma unroll
        for (int i = 0; i < (8 * BN) / 256; ++i) {
            int id = tid + i * 256;
            int kr = id / CT, c4 = (id % CT) * 4;
            *(float4*)&Bs[kr][c4] = *(const float4*)(W + (size_t)(k0 + kr) * BN + c4);
        }
        __syncthreads();
        #pragma unroll
        for (int k = 0; k < BK; ++k) {
            float4 b = *(float4*)&Bs[k][tcol];
            #pragma unroll
            for (int r = 0; r < 8; r++) {
                float a = As[k][trow + r];
                acc[r][0] += a * b.x; acc[r][1] += a * b.y;
                acc[r][2] += a * b.z; acc[r][3] += a * b.w;
            }
        }
        __syncthreads();
    }
    float b0 = bias[tcol], b1 = bias[tcol + 1], b2 = bias[tcol + 2], b3 = bias[tcol + 3];
    #pragma unroll
    for (int r = 0; r < 8; r++) {
        int gr = row0 + trow + r;
        if (gr >= M) break;
        float4 o = make_float4(acc[r][0] + b0, acc[r][1] + b1, acc[r][2] + b2, acc[r][3] + b3);
        *(float4*)(Out + (size_t)gr * BN + tcol) = o;
    }
}

// ---------------- host orchestration ----------------
static inline int nb128(int m) { return (m + 127) / 128; }

extern "C" void kernel_launch(void* const* d_in, const int* in_sizes, int n_in,
                              void* d_out, int out_size)
{
    const float* x_in[3] = {(const float*)d_in[0], (const float*)d_in[1], (const float*)d_in[2]};
    const int* esrc[4] = {(const int*)d_in[3], (const int*)d_in[5], (const int*)d_in[7], (const int*)d_in[9]};
    const int* edst[4] = {(const int*)d_in[4], (const int*)d_in[6], (const int*)d_in[8], (const int*)d_in[10]};
    const float* lin_w = (const float*)d_in[11];
    const float* lin_b = (const float*)d_in[12];
    const float* kw    = (const float*)d_in[13];
    const float* qw    = (const float*)d_in[14];
    const float* vw    = (const float*)d_in[15];
    const float* aw    = (const float*)d_in[16];
    const float* kb    = (const float*)d_in[17];
    const float* qb    = (const float*)d_in[18];
    const float* vb    = (const float*)d_in[19];
    const float* ab    = (const float*)d_in[20];
    const float* a_rel = (const float*)d_in[21];
    const float* m_rel = (const float*)d_in[22];
    const float* p_rel = (const float*)d_in[23];
    const float* skip  = (const float*)d_in[24];
    const float* out_w = (const float*)d_in[25];
    const float* out_b = (const float*)d_in[26];
    float* out = (float*)d_out;

    float *xs, *q, *agg, *ket, *vet, *alpha, *kwc, *vwc, *kbc, *vbc;
    int *cnt, *off, *woff, *part, *ssrc;
    cudaGetSymbolAddress((void**)&xs,   g_xs);
    cudaGetSymbolAddress((void**)&q,    g_q);
    cudaGetSymbolAddress((void**)&agg,  g_agg);
    cudaGetSymbolAddress((void**)&ket,  g_ket);
    cudaGetSymbolAddress((void**)&vet,  g_vet);
    cudaGetSymbolAddress((void**)&alpha,g_alpha);
    cudaGetSymbolAddress((void**)&cnt,  g_cnt);
    cudaGetSymbolAddress((void**)&off,  g_off);
    cudaGetSymbolAddress((void**)&woff, g_woff);
    cudaGetSymbolAddress((void**)&part, g_part);
    cudaGetSymbolAddress((void**)&ssrc, g_ssrc);
    cudaGetSymbolAddress((void**)&kwc,  g_kwc);
    cudaGetSymbolAddress((void**)&vwc,  g_vwc);
    cudaGetSymbolAddress((void**)&kbc,  g_kbc);
    cudaGetSymbolAddress((void**)&vbc,  g_vbc);

    cudaFuncSetAttribute(gemm_tf32_jobs, cudaFuncAttributeMaxDynamicSharedMemorySize, GEMM_SMEM);

    // ---- CSR build (edges are layer-invariant: build once) ----
    static const int DOFFh[4] = {DOFF0, DOFF1, DOFF2, DOFF3};
    cudaMemsetAsync(cnt, 0, DROWS * sizeof(int));
    for (int et = 0; et < 4; et++)
        hist_kernel<<<(NEh[et] + 255) / 256, 256>>>(edst[et], NEh[et], cnt + DOFFh[et]);
    scan_block<<<(DROWS + 1023) / 1024, 1024>>>(cnt, off, part);
    scan_part<<<1, 32>>>(part, (DROWS + 1023) / 1024);
    scan_add<<<(DROWS + 256) / 256, 256>>>(off, part, woff);
    for (int et = 0; et < 4; et++)
        scatter_kernel<<<(NEh[et] + 255) / 256, 256>>>(esrc[et], edst[et], NEh[et],
                                                       woff + DOFFh[et], ssrc);

    wcomb_kernel<<<8, 256>>>(kw, kb, vw, vb, a_rel, m_rel);

    // ---- input linear + relu (3 jobs, one launch) ----
    {
        Jobs11 js{}; int nj = 0, blk = 0;
        for (int i = 0; i < 3; i++) {
            GemmJob& J = js.j[nj++];
            J.A = x_in[i]; J.W = lin_w + (size_t)i * C * C; J.bias = lin_b + i * C;
            J.Out = xs + (size_t)XOFF[i] * C; J.M = NNh[i]; J.blk0 = blk; J.epi = 1;
            J.skipx = nullptr; J.skipv = nullptr;
            blk += nb128(NNh[i]);
        }
        gemm_tf32_jobs<<<blk, 256, GEMM_SMEM>>>(js, nj);
    }

    static const int KOFFh[4] = {KOFF0, KOFF1, KOFF2, KOFF3};
    for (int l = 0; l < NLAYER; l++) {
        // ---- Q + K_et + V_et projections (11 jobs, one launch) ----
        {
            Jobs11 js{}; int nj = 0, blk = 0;
            for (int i = 0; i < 3; i++) {
                GemmJob& J = js.j[nj++];
                J.A = xs + (size_t)XOFF[i] * C;
                J.W = qw + (size_t)(l * 3 + i) * C * C;
                J.bias = qb + (l * 3 + i) * C;
                J.Out = q + (size_t)XOFF[i] * C;
                J.M = NNh[i]; J.blk0 = blk; J.epi = 0;
                blk += nb128(NNh[i]);
            }
            for (int et = 0; et < 4; et++) {
                int si = ESRC[et];
                {
                    GemmJob& J = js.j[nj++];
                    J.A = xs + (size_t)XOFF[si] * C;
                    J.W = kwc + (size_t)(l * 4 + et) * C * C;
                    J.bias = kbc + (l * 4 + et) * C;
                    J.Out = ket + (size_t)KOFFh[et] * C;
                    J.M = NNh[si]; J.blk0 = blk; J.epi = 0;
                    blk += nb128(NNh[si]);
                }
                {
                    GemmJob& J = js.j[nj++];
                    J.A = xs + (size_t)XOFF[si] * C;
                    J.W = vwc + (size_t)(l * 4 + et) * C * C;
                    J.bias = vbc + (l * 4 + et) * C;
                    J.Out = vet + (size_t)KOFFh[et] * C;
                    J.M = NNh[si]; J.blk0 = blk; J.epi = 0;
                    blk += nb128(NNh[si]);
                }
            }
            gemm_tf32_jobs<<<blk, 256, GEMM_SMEM>>>(js, nj);
        }

        // ---- fused attention (no atomics, direct agg writes) ----
        attn_fused<<<(NTOT * 32 + 255) / 256, 256>>>(q, ket, vet, off, alpha, agg, p_rel, l);

        // ---- attn-out projection, gelu fused on A, skip-gate + relu epilogue ----
        {
            Jobs11 js{}; int nj = 0, blk = 0;
            for (int i = 0; i < 3; i++) {
                GemmJob& J = js.j[nj++];
                J.A = agg + (size_t)XOFF[i] * C;
                J.W = aw + (size_t)(l * 3 + i) * C * C;
                J.bias = ab + (l * 3 + i) * C;
                J.Out = xs + (size_t)XOFF[i] * C;
                J.skipx = xs + (size_t)XOFF[i] * C;
                J.skipv = skip + l * 3 + i;
                J.M = NNh[i]; J.blk0 = blk; J.epi = 2 | 4;
                blk += nb128(NNh[i]);
            }
            gemm_tf32_jobs<<<blk, 256, GEMM_SMEM>>>(js, nj);
        }
    }

    // ---- final output projection [N,128] @ [128,64] ----
    for (int i = 0; i < 3; i++) {
        dim3 grid((NNh[i] + 127) / 128);
        gemm_out64<<<grid, 256>>>(xs + (size_t)XOFF[i] * C, out_w, out_b,
                                  out + (size_t)XOFF[i] * OUTC, NNh[i]);
    }
}

// round 5
// speedup vs baseline: 1.8506x; 1.2368x over previous
#include <cuda_runtime.h>
#include <cuda_bf16.h>
#include <cstdint>

// ---------------- problem constants ----------------
#define C 128
#define H 8
#define DD 16
#define OUTC 64
#define NLAYER 2

static const int NNh[3]  = {30000, 60000, 6000};
static const int XOFF[3] = {0, 30000, 90000};
#define NTOT 96000
static const int NEh[4]  = {200000, 300000, 200000, 100000};
#define ETOT 800000
static const int ESRC[4] = {0, 1, 1, 2};
// dst types per et: 1,1,2,0
#define DOFF0 0
#define DOFF1 60000
#define DOFF2 120000
#define DOFF3 126000
#define DROWS 156000
#define KOFF0 0
#define KOFF1 30000
#define KOFF2 90000
#define KOFF3 150000
#define KETROWS 156000

// ---------------- scratch (device globals; no allocation allowed) ----------------
__device__ float    g_xs   [NTOT * C];
__device__ float    g_q    [NTOT * C];
__device__ float    g_agg  [NTOT * C];
__device__ float    g_ket  [KETROWS * C];
__device__ float    g_vet  [KETROWS * C];
__device__ int      g_cnt  [DROWS];
__device__ int      g_off  [DROWS + 1];
__device__ int      g_woff [DROWS];
__device__ int      g_part [256];
__device__ int      g_ssrc [ETOT];
__device__ float    g_kwc  [NLAYER * 4 * C * C];
__device__ float    g_vwc  [NLAYER * 4 * C * C];
__device__ float    g_kbc  [NLAYER * 4 * C];
__device__ float    g_vbc  [NLAYER * 4 * C];

// ---------------- helpers ----------------
__device__ __forceinline__ float gelu_tanh(float x) {
    float x3 = x * x * x;
    return 0.5f * x * (1.0f + tanhf(0.7978845608028654f * (x + 0.044715f * x3)));
}
// split fp32 into two packed bf16x2 words (hi keeps top 8 mantissa bits, lo the next 8)
__device__ __forceinline__ void bf16x3_pack(float x, float y, uint32_t& hi, uint32_t& lo) {
    __nv_bfloat16 hx = __float2bfloat16_rn(x);
    __nv_bfloat16 hy = __float2bfloat16_rn(y);
    __nv_bfloat16 lx = __float2bfloat16_rn(x - __bfloat162float(hx));
    __nv_bfloat16 ly = __float2bfloat16_rn(y - __bfloat162float(hy));
    __nv_bfloat162 hp; hp.x = hx; hp.y = hy;
    __nv_bfloat162 lp; lp.x = lx; lp.y = ly;
    hi = *(uint32_t*)&hp;
    lo = *(uint32_t*)&lp;
}
__device__ __forceinline__ void mma_bf16(float* c, const uint32_t a[4], uint32_t b0, uint32_t b1) {
    asm volatile("mma.sync.aligned.m16n8k16.row.col.f32.bf16.bf16.f32 "
                 "{%0,%1,%2,%3}, {%4,%5,%6,%7}, {%8,%9}, {%0,%1,%2,%3};"
                 : "+f"(c[0]), "+f"(c[1]), "+f"(c[2]), "+f"(c[3])
                 : "r"(a[0]), "r"(a[1]), "r"(a[2]), "r"(a[3]), "r"(b0), "r"(b1));
}

// ---------------- combined K/V weights (fold a_rel / m_rel into kw / vw) ----------------
__global__ void wcomb_kernel(const float* __restrict__ kw, const float* __restrict__ kb,
                             const float* __restrict__ vw, const float* __restrict__ vb,
                             const float* __restrict__ a_rel, const float* __restrict__ m_rel)
{
    int b  = blockIdx.x;          // 0..7 == l*4+et
    int l  = b >> 2, et = b & 3;
    int si = (et == 0) ? 0 : ((et == 3) ? 2 : 1);
    const float* KW = kw + (size_t)(l * 3 + si) * C * C;
    const float* VW = vw + (size_t)(l * 3 + si) * C * C;
    const float* KB = kb + (size_t)(l * 3 + si) * C;
    const float* VB = vb + (size_t)(l * 3 + si) * C;
    const float* AR = a_rel + (size_t)b * H * DD * DD;
    const float* MR = m_rel + (size_t)b * H * DD * DD;
    float* KWC = g_kwc + (size_t)b * C * C;
    float* VWC = g_vwc + (size_t)b * C * C;

    for (int idx = threadIdx.x; idx < C * C; idx += blockDim.x) {
        int c = idx >> 7, hf = idx & 127, h = hf >> 4, f = hf & 15;
        float sk = 0.f, sv = 0.f;
        #pragma unroll
        for (int d = 0; d < DD; d++) {
            sk += KW[c * C + h * DD + d] * AR[(h * DD + d) * DD + f];
            sv += VW[c * C + h * DD + d] * MR[(h * DD + d) * DD + f];
        }
        KWC[idx] = sk; VWC[idx] = sv;
    }
    if (threadIdx.x < C) {
        int hf = threadIdx.x, h = hf >> 4, f = hf & 15;
        float sk = 0.f, sv = 0.f;
        #pragma unroll
        for (int d = 0; d < DD; d++) {
            sk += KB[h * DD + d] * AR[(h * DD + d) * DD + f];
            sv += VB[h * DD + d] * MR[(h * DD + d) * DD + f];
        }
        g_kbc[b * C + hf] = sk; g_vbc[b * C + hf] = sv;
    }
}

// ---------------- CSR build: histogram -> scan -> scatter ----------------
__global__ void hist_kernel(const int* __restrict__ dst, int E, int* __restrict__ cnt)
{
    int i = blockIdx.x * 256 + threadIdx.x;
    if (i < E) atomicAdd(&cnt[dst[i]], 1);
}

__global__ void scan_block(const int* __restrict__ cnt, int* __restrict__ off, int* __restrict__ part)
{
    __shared__ int sm[1024];
    int tid = threadIdx.x;
    int i = blockIdx.x * 1024 + tid;
    int v = (i < DROWS) ? cnt[i] : 0;
    sm[tid] = v;
    __syncthreads();
    #pragma unroll
    for (int ofs = 1; ofs < 1024; ofs <<= 1) {
        int t = (tid >= ofs) ? sm[tid - ofs] : 0;
        __syncthreads();
        sm[tid] += t;
        __syncthreads();
    }
    if (i < DROWS) off[i] = sm[tid] - v;
    if (tid == 1023) part[blockIdx.x] = sm[1023];
}

__global__ void scan_part(int* part, int nb)
{
    if (threadIdx.x == 0 && blockIdx.x == 0) {
        int s = 0;
        for (int i = 0; i < nb; i++) { int t = part[i]; part[i] = s; s += t; }
    }
}

__global__ void scan_add(int* __restrict__ off, const int* __restrict__ part,
                         int* __restrict__ woff)
{
    int i = blockIdx.x * 256 + threadIdx.x;
    if (i < DROWS) {
        int o = off[i] + part[i >> 10];
        off[i] = o;
        woff[i] = o;
    }
    if (i == DROWS) off[DROWS] = ETOT;
}

__global__ void scatter_kernel(const int* __restrict__ src, const int* __restrict__ dst,
                               int E, int* __restrict__ woffb, int* __restrict__ ssrc)
{
    int i = blockIdx.x * 256 + threadIdx.x;
    if (i < E) {
        int p = atomicAdd(&woffb[dst[i]], 1);
        ssrc[p] = src[i];
    }
}

// ---------------- fused attention: one warp per dst node, online softmax, no atomics ----------------
__device__ __forceinline__ void attn_sweep(
    const float4 q4, int lane,
    int beg, int end, int koff,
    const float* __restrict__ ket, const float* __restrict__ vet,
    float ps, float4& accOut)
{
    float m = -1e30f, den = 0.f;
    float4 a = make_float4(0.f, 0.f, 0.f, 0.f);
    int s = (beg < end) ? __ldg(&g_ssrc[beg]) : 0;
    for (int p = beg; p < end; p++) {
        int sn = (p + 1 < end) ? __ldg(&g_ssrc[p + 1]) : 0;
        float4 k4 = ((const float4*)(ket + (size_t)(koff + s) * 128))[lane];
        float4 v4 = ((const float4*)(vet + (size_t)(koff + s) * 128))[lane];
        float dt = q4.x * k4.x + q4.y * k4.y + q4.z * k4.z + q4.w * k4.w;
        dt += __shfl_xor_sync(0xffffffffu, dt, 1);
        dt += __shfl_xor_sync(0xffffffffu, dt, 2);
        float al = dt * ps;
        float mn = fmaxf(m, al);
        float sc = __expf(m - mn);       // ==1 when max unchanged
        float ex = __expf(al - mn);
        den = den * sc + ex;
        a.x = a.x * sc + ex * v4.x;
        a.y = a.y * sc + ex * v4.y;
        a.z = a.z * sc + ex * v4.z;
        a.w = a.w * sc + ex * v4.w;
        m = mn;
        s = sn;
    }
    float w = 1.f / (den + 1e-16f);
    accOut.x += a.x * w; accOut.y += a.y * w;
    accOut.z += a.z * w; accOut.w += a.w * w;
}

__global__ void __launch_bounds__(256)
attn_fused(const float* __restrict__ q, const float* __restrict__ ket,
           const float* __restrict__ vet, const int* __restrict__ off,
           float* __restrict__ agg, const float* __restrict__ p_rel, int layer)
{
    int w = (blockIdx.x * 256 + threadIdx.x) >> 5;
    if (w >= NTOT) return;
    int lane = threadIdx.x & 31;
    int h = lane >> 2;

    float4 acc = make_float4(0.f, 0.f, 0.f, 0.f);
    int node;

    if (w < 60000) {
        int d = w;
        node = 30000 + d;
        float4 q4 = ((const float4*)(q + (size_t)node * 128))[lane];
        attn_sweep(q4, lane, off[DOFF0 + d], off[DOFF0 + d + 1], KOFF0, ket, vet,
                   p_rel[(layer * 4 + 0) * H + h] * 0.25f, acc);
        attn_sweep(q4, lane, off[DOFF1 + d], off[DOFF1 + d + 1], KOFF1, ket, vet,
                   p_rel[(layer * 4 + 1) * H + h] * 0.25f, acc);
    } else if (w < 90000) {
        int d = w - 60000;
        node = d;
        float4 q4 = ((const float4*)(q + (size_t)node * 128))[lane];
        attn_sweep(q4, lane, off[DOFF3 + d], off[DOFF3 + d + 1], KOFF3, ket, vet,
                   p_rel[(layer * 4 + 3) * H + h] * 0.25f, acc);
    } else {
        int d = w - 90000;
        node = 90000 + d;
        float4 q4 = ((const float4*)(q + (size_t)node * 128))[lane];
        attn_sweep(q4, lane, off[DOFF2 + d], off[DOFF2 + d + 1], KOFF2, ket, vet,
                   p_rel[(layer * 4 + 2) * H + h] * 0.25f, acc);
    }
    ((float4*)(agg + (size_t)node * 128))[lane] = acc;
}

// ---------------- multi-job bf16x3 tensor-core GEMM: Out[M,128] = A[M,128] @ W[128,128] ----------------
// epi bits: 0x1 relu, 0x2 skip-gate, 0x4 gelu on A load
struct GemmJob {
    const float *A, *W, *bias;
    float *Out;
    const float *skipx, *skipv;
    int M, blk0, epi;
    int _pad;
};
struct Jobs11 { GemmJob j[11]; };

#define APK 36     // uint32 stride: 32 k-pairs + pad
#define BPK 136    // uint32 stride: 128 cols + pad
#define A_HI 0
#define A_LO (128 * APK)
#define B_HI (2 * 128 * APK)
#define B_LO (2 * 128 * APK + 32 * BPK)
#define GEMM_SMEM ((2 * 128 * APK + 2 * 32 * BPK) * 4)

__global__ void __launch_bounds__(256)
gemm_bf16x3_jobs(Jobs11 jobs, int njobs)
{
    extern __shared__ uint32_t sm[];

    int bid = blockIdx.x;
    int j = 0;
    while (j + 1 < njobs && bid >= jobs.j[j + 1].blk0) j++;
    const GemmJob& J = jobs.j[j];

    int tid  = threadIdx.x;
    int lane = tid & 31, warp = tid >> 5;
    int wm = warp & 1, wn = warp >> 1;     // 2 x 4 warp grid, warp tile 64x32
    int g = lane >> 2, t = lane & 3;
    int row0 = (bid - J.blk0) * 128;
    bool doGelu = (J.epi & 4) != 0;

    float acc[4][4][4];
    #pragma unroll
    for (int a = 0; a < 4; a++)
        #pragma unroll
        for (int b = 0; b < 4; b++)
            #pragma unroll
            for (int c = 0; c < 4; c++) acc[a][b][c] = 0.f;

    #pragma unroll
    for (int ch = 0; ch < 2; ch++) {
        int k0 = ch * 64;
        // ---- A tile: 128 rows x 64 k, split+pack to bf16 hi/lo pairs ----
        {
            int r  = tid >> 4;            // 0..15
            int c4 = (tid & 15) * 4;      // 0..60 (k offset)
            #pragma unroll
            for (int p = 0; p < 8; p++) {
                int rr = r + p * 16;
                int gr = row0 + rr;
                float4 v = make_float4(0.f, 0.f, 0.f, 0.f);
                if (gr < J.M) v = *(const float4*)(J.A + (size_t)gr * 128 + k0 + c4);
                if (doGelu) {
                    v.x = gelu_tanh(v.x); v.y = gelu_tanh(v.y);
                    v.z = gelu_tanh(v.z); v.w = gelu_tanh(v.w);
                }
                uint32_t h0, l0, h1, l1;
                bf16x3_pack(v.x, v.y, h0, l0);
                bf16x3_pack(v.z, v.w, h1, l1);
                int base = rr * APK + (c4 >> 1);
                *(uint2*)&sm[A_HI + base] = make_uint2(h0, h1);
                *(uint2*)&sm[A_LO + base] = make_uint2(l0, l1);
            }
        }
        // ---- B tile: 64 k x 128 n, pack pairs along k ----
        {
            int kp0 = tid >> 5;           // 0..7
            int c4  = (tid & 31) * 4;     // 0..124
            #pragma unroll
            for (int p = 0; p < 4; p++) {
                int kp = kp0 + p * 8;     // pair index 0..31
                float4 e = *(const float4*)(J.W + (size_t)(k0 + 2 * kp)     * 128 + c4);
                float4 o = *(const float4*)(J.W + (size_t)(k0 + 2 * kp + 1) * 128 + c4);
                uint4 hv, lv;
                bf16x3_pack(e.x, o.x, hv.x, lv.x);
                bf16x3_pack(e.y, o.y, hv.y, lv.y);
                bf16x3_pack(e.z, o.z, hv.z, lv.z);
                bf16x3_pack(e.w, o.w, hv.w, lv.w);
                int base = kp * BPK + c4;
                *(uint4*)&sm[B_HI + base] = hv;
                *(uint4*)&sm[B_LO + base] = lv;
            }
        }
        __syncthreads();

        #pragma unroll
        for (int ks = 0; ks < 4; ks++) {      // 4 x k16 steps per 64-k chunk
            int kp = ks * 8;                  // pair base
            uint32_t ahi[4][4], alo[4][4];
            #pragma unroll
            for (int mf = 0; mf < 4; mf++) {
                int rm = wm * 64 + mf * 16;
                int i0 = (rm + g)     * APK + kp + t;
                int i1 = (rm + g + 8) * APK + kp + t;
                ahi[mf][0] = sm[A_HI + i0];
                ahi[mf][1] = sm[A_HI + i1];
                ahi[mf][2] = sm[A_HI + i0 + 4];
                ahi[mf][3] = sm[A_HI + i1 + 4];
                alo[mf][0] = sm[A_LO + i0];
                alo[mf][1] = sm[A_LO + i1];
                alo[mf][2] = sm[A_LO + i0 + 4];
                alo[mf][3] = sm[A_LO + i1 + 4];
            }
            #pragma unroll
            for (int nf = 0; nf < 4; nf++) {
                int cn = wn * 32 + nf * 8 + g;
                uint32_t bh0 = sm[B_HI + (kp + t)     * BPK + cn];
                uint32_t bh1 = sm[B_HI + (kp + t + 4) * BPK + cn];
                uint32_t bl0 = sm[B_LO + (kp + t)     * BPK + cn];
                uint32_t bl1 = sm[B_LO + (kp + t + 4) * BPK + cn];
                #pragma unroll
                for (int mf = 0; mf < 4; mf++) {
                    mma_bf16(acc[mf][nf], ahi[mf], bh0, bh1);
                    mma_bf16(acc[mf][nf], ahi[mf], bl0, bl1);
                    mma_bf16(acc[mf][nf], alo[mf], bh0, bh1);
                }
            }
        }
        __syncthreads();
    }

    // epilogue
    float beta = 1.f, omb = 0.f;
    if (J.epi & 2) {
        float sv = *J.skipv;
        beta = 1.f / (1.f + __expf(-sv));
        omb  = 1.f - beta;
    }
    bool relu = (J.epi & 1) || (J.epi & 2);

    #pragma unroll
    for (int nf = 0; nf < 4; nf++) {
        int col = wn * 32 + nf * 8 + t * 2;
        float bc0 = J.bias[col], bc1 = J.bias[col + 1];
        #pragma unroll
        for (int mf = 0; mf < 4; mf++) {
            int r0 = row0 + wm * 64 + mf * 16 + g;
            int r1 = r0 + 8;
            float o00 = acc[mf][nf][0] + bc0, o01 = acc[mf][nf][1] + bc1;
            float o10 = acc[mf][nf][2] + bc0, o11 = acc[mf][nf][3] + bc1;
            if (J.epi & 2) {
                if (r0 < J.M) {
                    float2 s = *(const float2*)(J.skipx + (size_t)r0 * 128 + col);
                    o00 = beta * o00 + omb * s.x;
                    o01 = beta * o01 + omb * s.y;
                }
                if (r1 < J.M) {
                    float2 s = *(const float2*)(J.skipx + (size_t)r1 * 128 + col);
                    o10 = beta * o10 + omb * s.x;
                    o11 = beta * o11 + omb * s.y;
                }
            }
            if (relu) {
                o00 = fmaxf(o00, 0.f); o01 = fmaxf(o01, 0.f);
                o10 = fmaxf(o10, 0.f); o11 = fmaxf(o11, 0.f);
            }
            if (r0 < J.M) *(float2*)(J.Out + (size_t)r0 * 128 + col) = make_float2(o00, o01);
            if (r1 < J.M) *(float2*)(J.Out + (size_t)r1 * 128 + col) = make_float2(o10, o11);
        }
    }
}

// ---------------- scalar GEMM for the final [128 x 64] projection ----------------
__global__ void __launch_bounds__(256)
gemm_out64(const float* __restrict__ A, const float* __restrict__ W,
           const float* __restrict__ bias, float* __restrict__ Out, int M)
{
    constexpr int BN = 64, CT = BN / 4, BM = (256 / CT) * 8, BK = 32, AP = BM + 4;
    __shared__ float As[BK][AP];
    __shared__ float Bs[BK][BN];

    int tid = threadIdx.x;
    int row0 = blockIdx.x * BM;
    int trow = (tid / CT) * 8;
    int tcol = (tid % CT) * 4;

    float acc[8][4];
    #pragma unroll
    for (int r = 0; r < 8; r++)
        #pragma unroll
        for (int c = 0; c < 4; c++) acc[r][c] = 0.f;

    for (int k0 = 0; k0 < 128; k0 += BK) {
        #pragma unroll
        for (int i = 0; i < (BM * 8) / 256; ++i) {
            int id = tid + i * 256;
            int r = id >> 3, kq = id & 7;
            float4 v = make_float4(0.f, 0.f, 0.f, 0.f);
            int gr = row0 + r;
            if (gr < M) v = *(const float4*)(A + (size_t)gr * 128 + k0 + kq * 4);
            As[kq * 4 + 0][r] = v.x; As[kq * 4 + 1][r] = v.y;
            As[kq * 4 + 2][r] = v.z; As[kq * 4 + 3][r] = v.w;
        }
        #pragma unroll
        for (int i = 0; i < (8 * BN) / 256; ++i) {
            int id = tid + i * 256;
            int kr = id / CT, c4 = (id % CT) * 4;
            *(float4*)&Bs[kr][c4] = *(const float4*)(W + (size_t)(k0 + kr) * BN + c4);
        }
        __syncthreads();
        #pragma unroll
        for (int k = 0; k < BK; ++k) {
            float4 b = *(float4*)&Bs[k][tcol];
            #pragma unroll
            for (int r = 0; r < 8; r++) {
                float a = As[k][trow + r];
                acc[r][0] += a * b.x; acc[r][1] += a * b.y;
                acc[r][2] += a * b.z; acc[r][3] += a * b.w;
            }
        }
        __syncthreads();
    }
    float b0 = bias[tcol], b1 = bias[tcol + 1], b2 = bias[tcol + 2], b3 = bias[tcol + 3];
    #pragma unroll
    for (int r = 0; r < 8; r++) {
        int gr = row0 + trow + r;
        if (gr >= M) break;
        float4 o = make_float4(acc[r][0] + b0, acc[r][1] + b1, acc[r][2] + b2, acc[r][3] + b3);
        *(float4*)(Out + (size_t)gr * BN + tcol) = o;
    }
}

// ---------------- host orchestration ----------------
static inline int nb128(int m) { return (m + 127) / 128; }

extern "C" void kernel_launch(void* const* d_in, const int* in_sizes, int n_in,
                              void* d_out, int out_size)
{
    const float* x_in[3] = {(const float*)d_in[0], (const float*)d_in[1], (const float*)d_in[2]};
    const int* esrc[4] = {(const int*)d_in[3], (const int*)d_in[5], (const int*)d_in[7], (const int*)d_in[9]};
    const int* edst[4] = {(const int*)d_in[4], (const int*)d_in[6], (const int*)d_in[8], (const int*)d_in[10]};
    const float* lin_w = (const float*)d_in[11];
    const float* lin_b = (const float*)d_in[12];
    const float* kw    = (const float*)d_in[13];
    const float* qw    = (const float*)d_in[14];
    const float* vw    = (const float*)d_in[15];
    const float* aw    = (const float*)d_in[16];
    const float* kb    = (const float*)d_in[17];
    const float* qb    = (const float*)d_in[18];
    const float* vb    = (const float*)d_in[19];
    const float* ab    = (const float*)d_in[20];
    const float* a_rel = (const float*)d_in[21];
    const float* m_rel = (const float*)d_in[22];
    const float* p_rel = (const float*)d_in[23];
    const float* skip  = (const float*)d_in[24];
    const float* out_w = (const float*)d_in[25];
    const float* out_b = (const float*)d_in[26];
    float* out = (float*)d_out;

    float *xs, *q, *agg, *ket, *vet, *kwc, *vwc, *kbc, *vbc;
    int *cnt, *off, *woff, *part, *ssrc;
    cudaGetSymbolAddress((void**)&xs,   g_xs);
    cudaGetSymbolAddress((void**)&q,    g_q);
    cudaGetSymbolAddress((void**)&agg,  g_agg);
    cudaGetSymbolAddress((void**)&ket,  g_ket);
    cudaGetSymbolAddress((void**)&vet,  g_vet);
    cudaGetSymbolAddress((void**)&cnt,  g_cnt);
    cudaGetSymbolAddress((void**)&off,  g_off);
    cudaGetSymbolAddress((void**)&woff, g_woff);
    cudaGetSymbolAddress((void**)&part, g_part);
    cudaGetSymbolAddress((void**)&ssrc, g_ssrc);
    cudaGetSymbolAddress((void**)&kwc,  g_kwc);
    cudaGetSymbolAddress((void**)&vwc,  g_vwc);
    cudaGetSymbolAddress((void**)&kbc,  g_kbc);
    cudaGetSymbolAddress((void**)&vbc,  g_vbc);

    cudaFuncSetAttribute(gemm_bf16x3_jobs, cudaFuncAttributeMaxDynamicSharedMemorySize, GEMM_SMEM);

    // ---- CSR build (edges are layer-invariant: build once) ----
    static const int DOFFh[4] = {DOFF0, DOFF1, DOFF2, DOFF3};
    cudaMemsetAsync(cnt, 0, DROWS * sizeof(int));
    for (int et = 0; et < 4; et++)
        hist_kernel<<<(NEh[et] + 255) / 256, 256>>>(edst[et], NEh[et], cnt + DOFFh[et]);
    scan_block<<<(DROWS + 1023) / 1024, 1024>>>(cnt, off, part);
    scan_part<<<1, 32>>>(part, (DROWS + 1023) / 1024);
    scan_add<<<(DROWS + 256) / 256, 256>>>(off, part, woff);
    for (int et = 0; et < 4; et++)
        scatter_kernel<<<(NEh[et] + 255) / 256, 256>>>(esrc[et], edst[et], NEh[et],
                                                       woff + DOFFh[et], ssrc);

    wcomb_kernel<<<8, 256>>>(kw, kb, vw, vb, a_rel, m_rel);

    // ---- input linear + relu (3 jobs, one launch) ----
    {
        Jobs11 js{}; int nj = 0, blk = 0;
        for (int i = 0; i < 3; i++) {
            GemmJob& J = js.j[nj++];
            J.A = x_in[i]; J.W = lin_w + (size_t)i * C * C; J.bias = lin_b + i * C;
            J.Out = xs + (size_t)XOFF[i] * C; J.M = NNh[i]; J.blk0 = blk; J.epi = 1;
            J.skipx = nullptr; J.skipv = nullptr;
            blk += nb128(NNh[i]);
        }
        gemm_bf16x3_jobs<<<blk, 256, GEMM_SMEM>>>(js, nj);
    }

    static const int KOFFh[4] = {KOFF0, KOFF1, KOFF2, KOFF3};
    for (int l = 0; l < NLAYER; l++) {
        // ---- Q + K_et + V_et projections (11 jobs, one launch) ----
        {
            Jobs11 js{}; int nj = 0, blk = 0;
            for (int i = 0; i < 3; i++) {
                GemmJob& J = js.j[nj++];
                J.A = xs + (size_t)XOFF[i] * C;
                J.W = qw + (size_t)(l * 3 + i) * C * C;
                J.bias = qb + (l * 3 + i) * C;
                J.Out = q + (size_t)XOFF[i] * C;
                J.M = NNh[i]; J.blk0 = blk; J.epi = 0;
                blk += nb128(NNh[i]);
            }
            for (int et = 0; et < 4; et++) {
                int si = ESRC[et];
                {
                    GemmJob& J = js.j[nj++];
                    J.A = xs + (size_t)XOFF[si] * C;
                    J.W = kwc + (size_t)(l * 4 + et) * C * C;
                    J.bias = kbc + (l * 4 + et) * C;
                    J.Out = ket + (size_t)KOFFh[et] * C;
                    J.M = NNh[si]; J.blk0 = blk; J.epi = 0;
                    blk += nb128(NNh[si]);
                }
                {
                    GemmJob& J = js.j[nj++];
                    J.A = xs + (size_t)XOFF[si] * C;
                    J.W = vwc + (size_t)(l * 4 + et) * C * C;
                    J.bias = vbc + (l * 4 + et) * C;
                    J.Out = vet + (size_t)KOFFh[et] * C;
                    J.M = NNh[si]; J.blk0 = blk; J.epi = 0;
                    blk += nb128(NNh[si]);
                }
            }
            gemm_bf16x3_jobs<<<blk, 256, GEMM_SMEM>>>(js, nj);
        }

        // ---- fused attention (online softmax, no atomics) ----
        attn_fused<<<(NTOT * 32 + 255) / 256, 256>>>(q, ket, vet, off, agg, p_rel, l);

        // ---- attn-out projection, gelu fused on A, skip-gate + relu epilogue ----
        {
            Jobs11 js{}; int nj = 0, blk = 0;
            for (int i = 0; i < 3; i++) {
                GemmJob& J = js.j[nj++];
                J.A = agg + (size_t)XOFF[i] * C;
                J.W = aw + (size_t)(l * 3 + i) * C * C;
                J.bias = ab + (l * 3 + i) * C;
                J.Out = xs + (size_t)XOFF[i] * C;
                J.skipx = xs + (size_t)XOFF[i] * C;
                J.skipv = skip + l * 3 + i;
                J.M = NNh[i]; J.blk0 = blk; J.epi = 2 | 4;
                blk += nb128(NNh[i]);
            }
            gemm_bf16x3_jobs<<<blk, 256, GEMM_SMEM>>>(js, nj);
        }
    }

    // ---- final output projection [N,128] @ [128,64] ----
    for (int i = 0; i < 3; i++) {
        dim3 grid((NNh[i] + 127) / 128);
        gemm_out64<<<grid, 256>>>(xs + (size_t)XOFF[i] * C, out_w, out_b,
                                  out + (size_t)XOFF[i] * OUTC, NNh[i]);
    }
}